// round 16
// baseline (speedup 1.0000x reference)
#include <cuda_runtime.h>
#include <cuda_fp16.h>
#include <cstdint>

#define NB 16
#define NA 128
#define CH 512
#define EF 30
#define KK 1024   // 2*CH

// device scratch (allocation-free, zero-initialized at load)
__device__ __half   g_h1h[(size_t)NB * NA * CH];    // h1 result, fp16 (masked rows stay 0)
__device__ __half   g_hh [(size_t)NB * NA * CH];    // h as fp16
__device__ __half   g_wWh[(size_t)CH * KK];         // w_W as fp16
__device__ uint32_t g_afrag[16 * 2 * 2 * 32 * 4];   // fW A-fragments
__device__ int      g_Mact;                         // # active node rows
__device__ int      g_rowidx[NB * NA];              // active rows first, then masked

__device__ __forceinline__ float selu_f(float x) {
    const float sc  = 1.0507009873554805f;
    const float sca = 1.7580993408473766f;  // scale*alpha
    float ex  = __expf(x);
    float neg = fmaf(ex, sca, -sca);
    float pos = sc * x;
    return (x > 0.0f) ? pos : neg;
}

__device__ __forceinline__ uint32_t smem_u32(const void* p) {
    uint32_t a;
    asm("{ .reg .u64 t; cvta.to.shared.u64 t, %1; cvt.u32.u64 %0, t; }" : "=r"(a) : "l"(p));
    return a;
}

#define LDSM_X4(r, addr) \
    asm volatile("ldmatrix.sync.aligned.m8n8.x4.shared.b16 {%0,%1,%2,%3}, [%4];" \
        : "=r"((r)[0]), "=r"((r)[1]), "=r"((r)[2]), "=r"((r)[3]) : "r"(addr))

__device__ __forceinline__ void mma_f16(float* d, uint32_t a0, uint32_t a1,
                                        uint32_t a2, uint32_t a3,
                                        uint32_t b0, uint32_t b1) {
    asm volatile(
        "mma.sync.aligned.m16n8k16.row.col.f32.f16.f16.f32 "
        "{%0,%1,%2,%3}, {%4,%5,%6,%7}, {%8,%9}, {%0,%1,%2,%3};"
        : "+f"(d[0]), "+f"(d[1]), "+f"(d[2]), "+f"(d[3])
        : "r"(a0), "r"(a1), "r"(a2), "r"(a3), "r"(b0), "r"(b1));
}

// =====================================================================
// Prep: block 0 = parallel row-compaction scan; blocks 1.. = fp16
// conversions + fW fragments + full out=h pre-copy.
// =====================================================================
__global__ void __launch_bounds__(256)
prep_kernel(const float* __restrict__ fW, const float* __restrict__ wW,
            const float* __restrict__ h, const float* __restrict__ nmask,
            float* __restrict__ out) {
    if (blockIdx.x == 0) {
        __shared__ int wsum[8];
        __shared__ int totalS;
        const int tt = threadIdx.x;
        const int l  = tt & 31;
        const int wg = tt >> 5;
        bool p[8];
        int local = 0;
#pragma unroll
        for (int q = 0; q < 8; q++) {
            p[q] = nmask[tt * 8 + q] > 0.5f;
            local += p[q];
        }
        int inc = local;
#pragma unroll
        for (int d = 1; d < 32; d <<= 1) {
            int v = __shfl_up_sync(0xffffffffu, inc, d);
            if (l >= d) inc += v;
        }
        if (l == 31) wsum[wg] = inc;
        __syncthreads();
        if (tt == 0) {
            int s = 0;
#pragma unroll
            for (int i = 0; i < 8; i++) { int c = wsum[i]; wsum[i] = s; s += c; }
            totalS = s;
            g_Mact = s;
        }
        __syncthreads();
        int aoff = wsum[wg] + inc - local;
        int moff = tt * 8 - aoff;
        const int M = totalS;
#pragma unroll
        for (int q = 0; q < 8; q++) {
            int r = tt * 8 + q;
            if (p[q]) g_rowidx[aoff++] = r;
            else      g_rowidx[M + moff++] = r;
        }
        return;
    }

    const int t = (blockIdx.x - 1) * 256 + threadIdx.x;   // 0 .. 262143

    // h -> fp16 + out = h pre-copy : one float4 per thread
    {
        float4 f = ((const float4*)h)[t];
        ((__half2*)g_hh)[t * 2]     = __floats2half2_rn(f.x, f.y);
        ((__half2*)g_hh)[t * 2 + 1] = __floats2half2_rn(f.z, f.w);
        ((float4*)out)[t] = f;
    }
    // wW -> fp16 : first half of threads
    if (t < (CH * KK) / 4) {
        float4 f = ((const float4*)wW)[t];
        ((__half2*)g_wWh)[t * 2]     = __floats2half2_rn(f.x, f.y);
        ((__half2*)g_wWh)[t * 2 + 1] = __floats2half2_rn(f.z, f.w);
    }
    // fW fragments
    if (t < 8192) {
        int r  = t & 3;
        int l  = (t >> 2) & 31;
        int ks = (t >> 7) & 1;
        int mt = (t >> 8) & 1;
        int cc = t >> 9;
        int row = cc * 32 + mt * 16 + (r & 1) * 8 + (l >> 2);
        int k   = ks * 16 + (r >> 1) * 8 + (l & 3) * 2;
        float v0 = (k     < EF) ? fW[row * EF + k]     : 0.0f;
        float v1 = (k + 1 < EF) ? fW[row * EF + k + 1] : 0.0f;
        __half2 hv = __floats2half2_rn(v0, v1);
        g_afrag[t] = *(uint32_t*)&hv;
    }
}

// =====================================================================
// Edge kernel (proven R15 form): one CTA per 4 compacted active rows.
// j compacted by edge_mask; scattered fp16 h gather; targeted zeroing;
// vectorized float2/half2 e-staging (8 threads per j-row).
// =====================================================================
#define EROWB 80

__global__ void __launch_bounds__(512, 2)
edge_mma_kernel(const float* __restrict__ e,
                const float* __restrict__ emask,
                const float* __restrict__ fb) {
    __shared__ __align__(16) char sE[4 * NA * EROWB];   // 40960 B
    __shared__ int   sJ[4][NA];
    __shared__ int   sNj[4];
    __shared__ int   sRowA[4];
    __shared__ int   sWc[4][4];

    const int tid = threadIdx.x;
    const int i0  = blockIdx.x * 4;
    const int Mact = g_Mact;
    if (i0 >= Mact) return;

    if (tid < 4) sRowA[tid] = (i0 + tid < Mact) ? g_rowidx[i0 + tid] : -1;
    __syncthreads();

    // ---- j compaction per group (g handles row sRowA[g]) ----
    const int g  = tid >> 7;
    const int t  = tid & 127;
    const int wg = (tid >> 5) & 3;
    const int l  = tid & 31;
    {
        const int row = sRowA[g];
        bool pred = false;
        if (row >= 0) pred = emask[(size_t)row * NA + t] > 0.5f;
        unsigned bal = __ballot_sync(0xffffffffu, pred);
        int pos = __popc(bal & ((1u << l) - 1u));
        if (l == 0) sWc[g][wg] = __popc(bal);
        __syncthreads();
        int off = 0;
#pragma unroll
        for (int k = 0; k < 3; k++) if (k < wg) off += sWc[g][k];
        if (pred) sJ[g][off + pos] = t;
        if (t == 0) sNj[g] = sWc[g][0] + sWc[g][1] + sWc[g][2] + sWc[g][3];
    }
    __syncthreads();

    // ---- targeted zeroing (reads sNj) ----
    {
        const int nj_g = sNj[g];
        char* rowp = sE + g * (NA * EROWB) + t * EROWB;
        *(uint32_t*)(rowp + 60) = 0u;   // pad word k=30,31
        const int c16 = (nj_g + 15) & ~15;
        if (t >= nj_g) {
            sJ[g][t] = 0;   // gather-index safety for tail slots
            if (t < c16) {
                uint4 z = make_uint4(0, 0, 0, 0);
                uint4* pr = (uint4*)rowp;
                pr[0] = z; pr[1] = z; pr[2] = z; pr[3] = z;
            }
        }
    }
    __syncthreads();   // sJ complete before staging reads it

    // ---- vectorized e staging: 8 threads per compacted j-row ----
    {
        const int row  = sRowA[g];
        const int nj_g = sNj[g];
        const int rsub = t >> 3;
        const int q    = t & 7;
        if (row >= 0) {
            const float* eg = e + (size_t)row * (NA * EF);
            char* sg = sE + g * (NA * EROWB);
            for (int s0 = 0; s0 < nj_g; s0 += 16) {
                int s = s0 + rsub;
                if (s < nj_g) {
                    int j = sJ[g][s];
                    const float2* src = (const float2*)(eg + j * EF);
                    char* dst = sg + s * EROWB;
                    float2 f0 = src[q];
                    *(__half2*)(dst + q * 4) = __floats2half2_rn(f0.x, f0.y);
                    if (q < 7) {
                        float2 f1 = src[q + 8];
                        *(__half2*)(dst + (q + 8) * 4) = __floats2half2_rn(f1.x, f1.y);
                    }
                }
            }
        }
    }
    __syncthreads();

    const int w     = tid >> 5;
    const int gid   = l >> 2;
    const int tig   = l & 3;
    const int cbase = w * 32;
    const int brow_off = ((l >> 4) << 3) + (l & 7);
    const int bkk_off  = ((l >> 3) & 1) << 3;

    uint4 AH[2][2];
#pragma unroll
    for (int mt = 0; mt < 2; mt++)
#pragma unroll
        for (int ks = 0; ks < 2; ks++)
            AH[mt][ks] = *(const uint4*)&g_afrag[(((w * 2 + mt) * 2 + ks) * 32 + l) * 4];

    float bias0[2], bias1[2];
#pragma unroll
    for (int mt = 0; mt < 2; mt++) {
        bias0[mt] = __ldg(fb + cbase + 16 * mt + gid);
        bias1[mt] = __ldg(fb + cbase + 16 * mt + gid + 8);
    }

    const uint32_t sbE = smem_u32(sE);

#pragma unroll 1
    for (int ii = 0; ii < 4; ii++) {
        const int row = sRowA[ii];
        if (row < 0) continue;
        const __half* hb = g_hh + (size_t)(row >> 7) * (NA * CH);   // b = row/128
        const int nj  = sNj[ii];
        const int nsc = (nj + 15) >> 4;
        float ps[4] = {0.f, 0.f, 0.f, 0.f};
        const uint32_t ebase = sbE + ii * (NA * EROWB);

#pragma unroll 1
        for (int sc = 0; sc < nsc; sc++) {
            const int j0 = sc * 16;
            uint32_t BH0[4], BH1[4];
            uint32_t jr = ebase + (uint32_t)(j0 + brow_off) * EROWB + bkk_off * 2;
            LDSM_X4(BH0, jr);        // k 0..15
            LDSM_X4(BH1, jr + 32);   // k 16..31

            int jsA[2], jsB[2];
            float em0[2], em1[2];
#pragma unroll
            for (int nt = 0; nt < 2; nt++) {
                const int slot = j0 + 8 * nt + 2 * tig;
                jsA[nt] = sJ[ii][slot];
                jsB[nt] = sJ[ii][slot + 1];
                em0[nt] = (slot     < nj) ? 1.0f : 0.0f;
                em1[nt] = (slot + 1 < nj) ? 1.0f : 0.0f;
            }
            float hv[2][2][4];
#pragma unroll
            for (int nt = 0; nt < 2; nt++)
#pragma unroll
                for (int mt = 0; mt < 2; mt++) {
                    const int c0 = cbase + 16 * mt + gid;
                    hv[nt][mt][0] = __half2float(__ldg(hb + (size_t)jsA[nt] * CH + c0));
                    hv[nt][mt][1] = __half2float(__ldg(hb + (size_t)jsB[nt] * CH + c0));
                    hv[nt][mt][2] = __half2float(__ldg(hb + (size_t)jsA[nt] * CH + c0 + 8));
                    hv[nt][mt][3] = __half2float(__ldg(hb + (size_t)jsB[nt] * CH + c0 + 8));
                }

            float acc[2][2][4];
#pragma unroll
            for (int mt = 0; mt < 2; mt++)
#pragma unroll
                for (int nt = 0; nt < 2; nt++) {
                    acc[mt][nt][0] = bias0[mt];
                    acc[mt][nt][1] = bias0[mt];
                    acc[mt][nt][2] = bias1[mt];
                    acc[mt][nt][3] = bias1[mt];
                }

#pragma unroll
            for (int mt = 0; mt < 2; mt++)
#pragma unroll
                for (int nt = 0; nt < 2; nt++) {
                    float* d = acc[mt][nt];
                    mma_f16(d, AH[mt][0].x, AH[mt][0].y, AH[mt][0].z, AH[mt][0].w,
                            BH0[nt * 2], BH0[nt * 2 + 1]);
                    mma_f16(d, AH[mt][1].x, AH[mt][1].y, AH[mt][1].z, AH[mt][1].w,
                            BH1[nt * 2], BH1[nt * 2 + 1]);
                }

#pragma unroll
            for (int nt = 0; nt < 2; nt++)
#pragma unroll
                for (int mt = 0; mt < 2; mt++) {
                    float s0 = selu_f(acc[mt][nt][0]) * em0[nt];
                    float s1 = selu_f(acc[mt][nt][1]) * em1[nt];
                    float s2 = selu_f(acc[mt][nt][2]) * em0[nt];
                    float s3 = selu_f(acc[mt][nt][3]) * em1[nt];
                    ps[mt * 2]     = fmaf(s0, hv[nt][mt][0], fmaf(s1, hv[nt][mt][1], ps[mt * 2]));
                    ps[mt * 2 + 1] = fmaf(s2, hv[nt][mt][2], fmaf(s3, hv[nt][mt][3], ps[mt * 2 + 1]));
                }
        }

#pragma unroll
        for (int i = 0; i < 4; i++) {
            ps[i] += __shfl_xor_sync(0xffffffffu, ps[i], 1);
            ps[i] += __shfl_xor_sync(0xffffffffu, ps[i], 2);
        }
        if (tig == 0) {
            __half* o = g_h1h + (size_t)row * CH;
#pragma unroll
            for (int mt = 0; mt < 2; mt++) {
                o[cbase + 16 * mt + gid]     = __float2half_rn(ps[mt * 2]);
                o[cbase + 16 * mt + gid + 8] = __float2half_rn(ps[mt * 2 + 1]);
            }
        }
    }
}

// =====================================================================
// Node MLP: 32x64 tiles (2x active CTAs => ~3.5 warps/SMSP), 8 warps =
// 2 m-warps x 4 n-warps, register-staged + double-buffered smem, one
// barrier per k-chunk.
// =====================================================================
#define NROWH 72

__global__ void __launch_bounds__(256)
node_mma_kernel(const float* __restrict__ h,
                const float* __restrict__ nmask,
                const float* __restrict__ wb,
                float* __restrict__ out) {
    __shared__ __align__(16) __half sA[2][32][NROWH];
    __shared__ __align__(16) __half sB[2][64][NROWH];
    __shared__ int sRow[32];

    const int n0  = blockIdx.x * 64;
    const int m0  = blockIdx.y * 32;
    const int tid = threadIdx.x;

    if (m0 >= g_Mact) return;   // out = h already pre-copied by prep

    if (tid < 32) sRow[tid] = g_rowidx[m0 + tid];
    __syncthreads();

    const int w   = tid >> 5;
    const int l   = tid & 31;
    const int gid = l >> 2;
    const int tig = l & 3;
    const int mw  = w >> 2;   // 0..1 : 16 m-rows per warp
    const int nwp = w & 3;    // 0..3 : 16 n-cols per warp

    float acc[2][4];
#pragma unroll
    for (int nt = 0; nt < 2; nt++) {
        int n = n0 + nwp * 16 + nt * 8 + tig * 2;
        float b0 = __ldg(wb + n), b1 = __ldg(wb + n + 1);
        acc[nt][0] = b0; acc[nt][1] = b1;
        acc[nt][2] = b0; acc[nt][3] = b1;
    }

    const int arow = mw * 16 + (l & 15);
    const int acol = (l >> 4) << 3;
    const int brow = nwp * 16 + ((l >> 4) << 3) + (l & 7);
    const int bcol = ((l >> 3) & 1) << 3;

    uint4 ld[3];
    int lrow[3], lseg[3], lisA[3];
#pragma unroll
    for (int q = 0; q < 3; q++) {
        int cid = q * 256 + tid;          // 0..767
        lisA[q] = (cid < 256);            // A: 32 rows x 8 segs
        int c2 = lisA[q] ? cid : cid - 256;
        lrow[q] = c2 >> 3;
        lseg[q] = c2 & 7;
    }

#define LOAD_TILE(kc) do { \
    _Pragma("unroll") \
    for (int q = 0; q < 3; q++) { \
        if (lisA[q]) { \
            int orig = sRow[lrow[q]]; \
            const __half* src = ((kc) < 8) \
                ? (g_hh  + (size_t)orig * CH + (kc) * 64 + lseg[q] * 8) \
                : (g_h1h + (size_t)orig * CH + ((kc) - 8) * 64 + lseg[q] * 8); \
            ld[q] = *(const uint4*)src; \
        } else { \
            ld[q] = *(const uint4*)(g_wWh + (size_t)(n0 + lrow[q]) * KK + (kc) * 64 + lseg[q] * 8); \
        } \
    } \
} while (0)

    LOAD_TILE(0);

#pragma unroll 1
    for (int kc = 0; kc < 16; kc++) {
        const int cur = kc & 1;
#pragma unroll
        for (int q = 0; q < 3; q++) {
            if (lisA[q]) *(uint4*)&sA[cur][lrow[q]][lseg[q] * 8] = ld[q];
            else         *(uint4*)&sB[cur][lrow[q]][lseg[q] * 8] = ld[q];
        }
        __syncthreads();   // single barrier per chunk (double-buffered)
        if (kc < 15) LOAD_TILE(kc + 1);   // global loads overlap MMA below

#pragma unroll
        for (int ks = 0; ks < 4; ks++) {
            uint32_t Af[4];
            LDSM_X4(Af, smem_u32(&sA[cur][arow][ks * 16 + acol]));
            uint32_t Bf[4];
            LDSM_X4(Bf, smem_u32(&sB[cur][brow][ks * 16 + bcol]));
            mma_f16(acc[0], Af[0], Af[1], Af[2], Af[3], Bf[0], Bf[1]);
            mma_f16(acc[1], Af[0], Af[1], Af[2], Af[3], Bf[2], Bf[3]);
        }
    }

    const int ms = mw * 16 + gid;
    const int r0 = sRow[ms];
    const int r1 = sRow[ms + 8];
    const float nm0 = __ldg(nmask + r0);
    const float nm1 = __ldg(nmask + r1);
#pragma unroll
    for (int nt = 0; nt < 2; nt++) {
        int n = n0 + nwp * 16 + nt * 8 + tig * 2;
        float2 hr0 = *(const float2*)(h + (size_t)r0 * CH + n);
        float2 hr1 = *(const float2*)(h + (size_t)r1 * CH + n);
        float2 o0, o1;
        o0.x = selu_f(acc[nt][0]) * nm0 + hr0.x;
        o0.y = selu_f(acc[nt][1]) * nm0 + hr0.y;
        o1.x = selu_f(acc[nt][2]) * nm1 + hr1.x;
        o1.y = selu_f(acc[nt][3]) * nm1 + hr1.y;
        *(float2*)(out + (size_t)r0 * CH + n) = o0;
        *(float2*)(out + (size_t)r1 * CH + n) = o1;
    }
}

// =====================================================================
extern "C" void kernel_launch(void* const* d_in, const int* in_sizes, int n_in,
                              void* d_out, int out_size) {
    (void)in_sizes; (void)n_in; (void)out_size;
    const float* h     = (const float*)d_in[0];
    const float* e     = (const float*)d_in[1];
    const float* nmask = (const float*)d_in[2];
    const float* emask = (const float*)d_in[3];
    const float* fW    = (const float*)d_in[4];
    const float* fb    = (const float*)d_in[5];
    const float* wW    = (const float*)d_in[6];
    const float* wb    = (const float*)d_in[7];
    float* out = (float*)d_out;

    prep_kernel<<<1025, 256>>>(fW, wW, h, nmask, out);
    edge_mma_kernel<<<(NB * NA + 3) / 4, 512>>>(e, emask, fb);
    node_mma_kernel<<<dim3(CH / 64, (NB * NA) / 32), 256>>>(h, nmask, wb, out);
}

// round 17
// speedup vs baseline: 1.1073x; 1.1073x over previous
#include <cuda_runtime.h>
#include <cuda_fp16.h>
#include <cstdint>

#define NB 16
#define NA 128
#define CH 512
#define EF 30
#define KK 1024   // 2*CH

// device scratch (allocation-free, zero-initialized at load)
__device__ __half   g_h1h[(size_t)NB * NA * CH];    // h1 result, fp16 (masked rows stay 0)
__device__ __half   g_hh [(size_t)NB * NA * CH];    // h as fp16
__device__ __half   g_wWh[(size_t)CH * KK];         // w_W as fp16
__device__ uint32_t g_afrag[16 * 2 * 2 * 32 * 4];   // fW A-fragments
__device__ int      g_Mact;                         // # active node rows
__device__ int      g_rowidx[NB * NA];              // active rows first, then masked

__device__ __forceinline__ float selu_f(float x) {
    const float sc  = 1.0507009873554805f;
    const float sca = 1.7580993408473766f;  // scale*alpha
    float ex  = __expf(x);
    float neg = fmaf(ex, sca, -sca);
    float pos = sc * x;
    return (x > 0.0f) ? pos : neg;
}

__device__ __forceinline__ uint32_t smem_u32(const void* p) {
    uint32_t a;
    asm("{ .reg .u64 t; cvta.to.shared.u64 t, %1; cvt.u32.u64 %0, t; }" : "=r"(a) : "l"(p));
    return a;
}

#define LDSM_X4(r, addr) \
    asm volatile("ldmatrix.sync.aligned.m8n8.x4.shared.b16 {%0,%1,%2,%3}, [%4];" \
        : "=r"((r)[0]), "=r"((r)[1]), "=r"((r)[2]), "=r"((r)[3]) : "r"(addr))

__device__ __forceinline__ void mma_f16(float* d, uint32_t a0, uint32_t a1,
                                        uint32_t a2, uint32_t a3,
                                        uint32_t b0, uint32_t b1) {
    asm volatile(
        "mma.sync.aligned.m16n8k16.row.col.f32.f16.f16.f32 "
        "{%0,%1,%2,%3}, {%4,%5,%6,%7}, {%8,%9}, {%0,%1,%2,%3};"
        : "+f"(d[0]), "+f"(d[1]), "+f"(d[2]), "+f"(d[3])
        : "r"(a0), "r"(a1), "r"(a2), "r"(a3), "r"(b0), "r"(b1));
}

// =====================================================================
// Prep: block 0 = parallel row-compaction scan; blocks 1.. = fp16
// conversions + fW fragments + full out=h pre-copy.
// =====================================================================
__global__ void __launch_bounds__(256)
prep_kernel(const float* __restrict__ fW, const float* __restrict__ wW,
            const float* __restrict__ h, const float* __restrict__ nmask,
            float* __restrict__ out) {
    if (blockIdx.x == 0) {
        __shared__ int wsum[8];
        __shared__ int totalS;
        const int tt = threadIdx.x;
        const int l  = tt & 31;
        const int wg = tt >> 5;
        bool p[8];
        int local = 0;
#pragma unroll
        for (int q = 0; q < 8; q++) {
            p[q] = nmask[tt * 8 + q] > 0.5f;
            local += p[q];
        }
        int inc = local;
#pragma unroll
        for (int d = 1; d < 32; d <<= 1) {
            int v = __shfl_up_sync(0xffffffffu, inc, d);
            if (l >= d) inc += v;
        }
        if (l == 31) wsum[wg] = inc;
        __syncthreads();
        if (tt == 0) {
            int s = 0;
#pragma unroll
            for (int i = 0; i < 8; i++) { int c = wsum[i]; wsum[i] = s; s += c; }
            totalS = s;
            g_Mact = s;
        }
        __syncthreads();
        int aoff = wsum[wg] + inc - local;
        int moff = tt * 8 - aoff;
        const int M = totalS;
#pragma unroll
        for (int q = 0; q < 8; q++) {
            int r = tt * 8 + q;
            if (p[q]) g_rowidx[aoff++] = r;
            else      g_rowidx[M + moff++] = r;
        }
        return;
    }

    const int t = (blockIdx.x - 1) * 256 + threadIdx.x;   // 0 .. 262143

    // h -> fp16 + out = h pre-copy : one float4 per thread
    {
        float4 f = ((const float4*)h)[t];
        ((__half2*)g_hh)[t * 2]     = __floats2half2_rn(f.x, f.y);
        ((__half2*)g_hh)[t * 2 + 1] = __floats2half2_rn(f.z, f.w);
        ((float4*)out)[t] = f;
    }
    // wW -> fp16 : first half of threads
    if (t < (CH * KK) / 4) {
        float4 f = ((const float4*)wW)[t];
        ((__half2*)g_wWh)[t * 2]     = __floats2half2_rn(f.x, f.y);
        ((__half2*)g_wWh)[t * 2 + 1] = __floats2half2_rn(f.z, f.w);
    }
    // fW fragments
    if (t < 8192) {
        int r  = t & 3;
        int l  = (t >> 2) & 31;
        int ks = (t >> 7) & 1;
        int mt = (t >> 8) & 1;
        int cc = t >> 9;
        int row = cc * 32 + mt * 16 + (r & 1) * 8 + (l >> 2);
        int k   = ks * 16 + (r >> 1) * 8 + (l & 3) * 2;
        float v0 = (k     < EF) ? fW[row * EF + k]     : 0.0f;
        float v1 = (k + 1 < EF) ? fW[row * EF + k + 1] : 0.0f;
        __half2 hv = __floats2half2_rn(v0, v1);
        g_afrag[t] = *(uint32_t*)&hv;
    }
}

// =====================================================================
// Edge kernel: one CTA per 4 compacted active rows. j compacted by
// edge_mask; scattered fp16 h gather; targeted zeroing MERGED with the
// vectorized float2/half2 e-staging phase (disjoint writes; one barrier).
// =====================================================================
#define EROWB 80

__global__ void __launch_bounds__(512, 2)
edge_mma_kernel(const float* __restrict__ e,
                const float* __restrict__ emask,
                const float* __restrict__ fb) {
    __shared__ __align__(16) char sE[4 * NA * EROWB];   // 40960 B
    __shared__ int   sJ[4][NA];
    __shared__ int   sNj[4];
    __shared__ int   sRowA[4];
    __shared__ int   sWc[4][4];

    const int tid = threadIdx.x;
    const int i0  = blockIdx.x * 4;
    const int Mact = g_Mact;
    if (i0 >= Mact) return;

    if (tid < 4) sRowA[tid] = (i0 + tid < Mact) ? g_rowidx[i0 + tid] : -1;
    __syncthreads();

    // ---- j compaction per group (g handles row sRowA[g]) ----
    const int g  = tid >> 7;
    const int t  = tid & 127;
    const int wg = (tid >> 5) & 3;
    const int l  = tid & 31;
    {
        const int row = sRowA[g];
        bool pred = false;
        if (row >= 0) pred = emask[(size_t)row * NA + t] > 0.5f;
        unsigned bal = __ballot_sync(0xffffffffu, pred);
        int pos = __popc(bal & ((1u << l) - 1u));
        if (l == 0) sWc[g][wg] = __popc(bal);
        __syncthreads();
        int off = 0;
#pragma unroll
        for (int k = 0; k < 3; k++) if (k < wg) off += sWc[g][k];
        if (pred) sJ[g][off + pos] = t;
        if (t == 0) sNj[g] = sWc[g][0] + sWc[g][1] + sWc[g][2] + sWc[g][3];
    }
    __syncthreads();

    // ---- merged zeroing + staging (disjoint writes; staging reads only
    //      sJ[s<nj] which compaction sealed above) ----
    {
        const int nj_g = sNj[g];
        // zeroing part: pad word of every row; tail rows [nj, ceil16(nj))
        char* rowp = sE + g * (NA * EROWB) + t * EROWB;
        *(uint32_t*)(rowp + 60) = 0u;
        const int c16 = (nj_g + 15) & ~15;
        if (t >= nj_g) {
            sJ[g][t] = 0;   // tail gather-index safety (staging never reads these)
            if (t < c16) {
                uint4 z = make_uint4(0, 0, 0, 0);
                uint4* pr = (uint4*)rowp;
                pr[0] = z; pr[1] = z; pr[2] = z; pr[3] = z;
            }
        }
        // staging part: 8 threads per compacted j-row, float2 -> half2
        const int row  = sRowA[g];
        const int rsub = t >> 3;
        const int q    = t & 7;
        if (row >= 0) {
            const float* eg = e + (size_t)row * (NA * EF);
            char* sg = sE + g * (NA * EROWB);
            for (int s0 = 0; s0 < nj_g; s0 += 16) {
                int s = s0 + rsub;
                if (s < nj_g) {
                    int j = sJ[g][s];
                    const float2* src = (const float2*)(eg + j * EF);
                    char* dst = sg + s * EROWB;
                    float2 f0 = src[q];
                    *(__half2*)(dst + q * 4) = __floats2half2_rn(f0.x, f0.y);
                    if (q < 7) {
                        float2 f1 = src[q + 8];
                        *(__half2*)(dst + (q + 8) * 4) = __floats2half2_rn(f1.x, f1.y);
                    }
                }
            }
        }
    }
    __syncthreads();

    const int w     = tid >> 5;
    const int gid   = l >> 2;
    const int tig   = l & 3;
    const int cbase = w * 32;
    const int brow_off = ((l >> 4) << 3) + (l & 7);
    const int bkk_off  = ((l >> 3) & 1) << 3;

    uint4 AH[2][2];
#pragma unroll
    for (int mt = 0; mt < 2; mt++)
#pragma unroll
        for (int ks = 0; ks < 2; ks++)
            AH[mt][ks] = *(const uint4*)&g_afrag[(((w * 2 + mt) * 2 + ks) * 32 + l) * 4];

    float bias0[2], bias1[2];
#pragma unroll
    for (int mt = 0; mt < 2; mt++) {
        bias0[mt] = __ldg(fb + cbase + 16 * mt + gid);
        bias1[mt] = __ldg(fb + cbase + 16 * mt + gid + 8);
    }

    const uint32_t sbE = smem_u32(sE);

#pragma unroll 1
    for (int ii = 0; ii < 4; ii++) {
        const int row = sRowA[ii];
        if (row < 0) continue;
        const __half* hb = g_hh + (size_t)(row >> 7) * (NA * CH);   // b = row/128
        const int nj  = sNj[ii];
        const int nsc = (nj + 15) >> 4;
        float ps[4] = {0.f, 0.f, 0.f, 0.f};
        const uint32_t ebase = sbE + ii * (NA * EROWB);

#pragma unroll 1
        for (int sc = 0; sc < nsc; sc++) {
            const int j0 = sc * 16;
            uint32_t BH0[4], BH1[4];
            uint32_t jr = ebase + (uint32_t)(j0 + brow_off) * EROWB + bkk_off * 2;
            LDSM_X4(BH0, jr);        // k 0..15
            LDSM_X4(BH1, jr + 32);   // k 16..31

            int jsA[2], jsB[2];
            float em0[2], em1[2];
#pragma unroll
            for (int nt = 0; nt < 2; nt++) {
                const int slot = j0 + 8 * nt + 2 * tig;
                jsA[nt] = sJ[ii][slot];
                jsB[nt] = sJ[ii][slot + 1];
                em0[nt] = (slot     < nj) ? 1.0f : 0.0f;
                em1[nt] = (slot + 1 < nj) ? 1.0f : 0.0f;
            }
            float hv[2][2][4];
#pragma unroll
            for (int nt = 0; nt < 2; nt++)
#pragma unroll
                for (int mt = 0; mt < 2; mt++) {
                    const int c0 = cbase + 16 * mt + gid;
                    hv[nt][mt][0] = __half2float(__ldg(hb + (size_t)jsA[nt] * CH + c0));
                    hv[nt][mt][1] = __half2float(__ldg(hb + (size_t)jsB[nt] * CH + c0));
                    hv[nt][mt][2] = __half2float(__ldg(hb + (size_t)jsA[nt] * CH + c0 + 8));
                    hv[nt][mt][3] = __half2float(__ldg(hb + (size_t)jsB[nt] * CH + c0 + 8));
                }

            float acc[2][2][4];
#pragma unroll
            for (int mt = 0; mt < 2; mt++)
#pragma unroll
                for (int nt = 0; nt < 2; nt++) {
                    acc[mt][nt][0] = bias0[mt];
                    acc[mt][nt][1] = bias0[mt];
                    acc[mt][nt][2] = bias1[mt];
                    acc[mt][nt][3] = bias1[mt];
                }

#pragma unroll
            for (int mt = 0; mt < 2; mt++)
#pragma unroll
                for (int nt = 0; nt < 2; nt++) {
                    float* d = acc[mt][nt];
                    mma_f16(d, AH[mt][0].x, AH[mt][0].y, AH[mt][0].z, AH[mt][0].w,
                            BH0[nt * 2], BH0[nt * 2 + 1]);
                    mma_f16(d, AH[mt][1].x, AH[mt][1].y, AH[mt][1].z, AH[mt][1].w,
                            BH1[nt * 2], BH1[nt * 2 + 1]);
                }

#pragma unroll
            for (int nt = 0; nt < 2; nt++)
#pragma unroll
                for (int mt = 0; mt < 2; mt++) {
                    float s0 = selu_f(acc[mt][nt][0]) * em0[nt];
                    float s1 = selu_f(acc[mt][nt][1]) * em1[nt];
                    float s2 = selu_f(acc[mt][nt][2]) * em0[nt];
                    float s3 = selu_f(acc[mt][nt][3]) * em1[nt];
                    ps[mt * 2]     = fmaf(s0, hv[nt][mt][0], fmaf(s1, hv[nt][mt][1], ps[mt * 2]));
                    ps[mt * 2 + 1] = fmaf(s2, hv[nt][mt][2], fmaf(s3, hv[nt][mt][3], ps[mt * 2 + 1]));
                }
        }

#pragma unroll
        for (int i = 0; i < 4; i++) {
            ps[i] += __shfl_xor_sync(0xffffffffu, ps[i], 1);
            ps[i] += __shfl_xor_sync(0xffffffffu, ps[i], 2);
        }
        if (tig == 0) {
            __half* o = g_h1h + (size_t)row * CH;
#pragma unroll
            for (int mt = 0; mt < 2; mt++) {
                o[cbase + 16 * mt + gid]     = __float2half_rn(ps[mt * 2]);
                o[cbase + 16 * mt + gid + 8] = __float2half_rn(ps[mt * 2 + 1]);
            }
        }
    }
}

// =====================================================================
// Node MLP (proven R15 64x64 form): register-staged loads + double-
// buffered smem, one barrier per k-chunk.
// =====================================================================
#define NROWH 72

__global__ void __launch_bounds__(256)
node_mma_kernel(const float* __restrict__ h,
                const float* __restrict__ nmask,
                const float* __restrict__ wb,
                float* __restrict__ out) {
    __shared__ __align__(16) __half sA[2][64][NROWH];
    __shared__ __align__(16) __half sB[2][64][NROWH];
    __shared__ int sRow[64];

    const int n0  = blockIdx.x * 64;
    const int m0  = blockIdx.y * 64;
    const int tid = threadIdx.x;

    if (m0 >= g_Mact) return;   // out = h already pre-copied by prep

    if (tid < 64) sRow[tid] = g_rowidx[m0 + tid];
    __syncthreads();

    const int w   = tid >> 5;
    const int l   = tid & 31;
    const int gid = l >> 2;
    const int tig = l & 3;
    const int mw  = w >> 1;
    const int nh  = w & 1;

    float acc[4][4];
#pragma unroll
    for (int nt = 0; nt < 4; nt++) {
        int n = n0 + nh * 32 + nt * 8 + tig * 2;
        float b0 = __ldg(wb + n), b1 = __ldg(wb + n + 1);
        acc[nt][0] = b0; acc[nt][1] = b1;
        acc[nt][2] = b0; acc[nt][3] = b1;
    }

    const int arow = mw * 16 + (l & 15);
    const int acol = (l >> 4) << 3;
    const int brow = nh * 32 + ((l >> 4) << 3) + (l & 7);
    const int bcol = ((l >> 3) & 1) << 3;

    uint4 ld[4];
    int lrow[4], lseg[4], lisA[4];
#pragma unroll
    for (int q = 0; q < 4; q++) {
        int cid = q * 256 + tid;
        lisA[q] = (cid < 512);
        int c2 = cid & 511;
        lrow[q] = c2 >> 3;
        lseg[q] = c2 & 7;
    }

#define LOAD_TILE(kc) do { \
    _Pragma("unroll") \
    for (int q = 0; q < 4; q++) { \
        if (lisA[q]) { \
            int orig = sRow[lrow[q]]; \
            const __half* src = ((kc) < 8) \
                ? (g_hh  + (size_t)orig * CH + (kc) * 64 + lseg[q] * 8) \
                : (g_h1h + (size_t)orig * CH + ((kc) - 8) * 64 + lseg[q] * 8); \
            ld[q] = *(const uint4*)src; \
        } else { \
            ld[q] = *(const uint4*)(g_wWh + (size_t)(n0 + lrow[q]) * KK + (kc) * 64 + lseg[q] * 8); \
        } \
    } \
} while (0)

    LOAD_TILE(0);

#pragma unroll 1
    for (int kc = 0; kc < 16; kc++) {
        const int cur = kc & 1;
        // STS staged regs into current buffer
#pragma unroll
        for (int q = 0; q < 4; q++) {
            if (lisA[q]) *(uint4*)&sA[cur][lrow[q]][lseg[q] * 8] = ld[q];
            else         *(uint4*)&sB[cur][lrow[q]][lseg[q] * 8] = ld[q];
        }
        __syncthreads();   // single barrier: orders STS(cur) before MMA reads,
                           // and MMA(cur,kc) before STS(cur,kc+2)
        if (kc < 15) LOAD_TILE(kc + 1);   // global loads overlap MMA below

#pragma unroll
        for (int ks = 0; ks < 4; ks++) {
            uint32_t Af[4];
            LDSM_X4(Af, smem_u32(&sA[cur][arow][ks * 16 + acol]));
            uint32_t Bf0[4], Bf1[4];
            LDSM_X4(Bf0, smem_u32(&sB[cur][brow][ks * 16 + bcol]));
            LDSM_X4(Bf1, smem_u32(&sB[cur][brow + 16][ks * 16 + bcol]));
            mma_f16(acc[0], Af[0], Af[1], Af[2], Af[3], Bf0[0], Bf0[1]);
            mma_f16(acc[1], Af[0], Af[1], Af[2], Af[3], Bf0[2], Bf0[3]);
            mma_f16(acc[2], Af[0], Af[1], Af[2], Af[3], Bf1[0], Bf1[1]);
            mma_f16(acc[3], Af[0], Af[1], Af[2], Af[3], Bf1[2], Bf1[3]);
        }
    }

    const int ms = mw * 16 + gid;
    const int r0 = sRow[ms];
    const int r1 = sRow[ms + 8];
    const float nm0 = __ldg(nmask + r0);
    const float nm1 = __ldg(nmask + r1);
#pragma unroll
    for (int nt = 0; nt < 4; nt++) {
        int n = n0 + nh * 32 + nt * 8 + tig * 2;
        float2 hr0 = *(const float2*)(h + (size_t)r0 * CH + n);
        float2 hr1 = *(const float2*)(h + (size_t)r1 * CH + n);
        float2 o0, o1;
        o0.x = selu_f(acc[nt][0]) * nm0 + hr0.x;
        o0.y = selu_f(acc[nt][1]) * nm0 + hr0.y;
        o1.x = selu_f(acc[nt][2]) * nm1 + hr1.x;
        o1.y = selu_f(acc[nt][3]) * nm1 + hr1.y;
        *(float2*)(out + (size_t)r0 * CH + n) = o0;
        *(float2*)(out + (size_t)r1 * CH + n) = o1;
    }
}

// =====================================================================
extern "C" void kernel_launch(void* const* d_in, const int* in_sizes, int n_in,
                              void* d_out, int out_size) {
    (void)in_sizes; (void)n_in; (void)out_size;
    const float* h     = (const float*)d_in[0];
    const float* e     = (const float*)d_in[1];
    const float* nmask = (const float*)d_in[2];
    const float* emask = (const float*)d_in[3];
    const float* fW    = (const float*)d_in[4];
    const float* fb    = (const float*)d_in[5];
    const float* wW    = (const float*)d_in[6];
    const float* wb    = (const float*)d_in[7];
    float* out = (float*)d_out;

    prep_kernel<<<1025, 256>>>(fW, wW, h, nmask, out);
    edge_mma_kernel<<<(NB * NA + 3) / 4, 512>>>(e, emask, fb);
    node_mma_kernel<<<dim3(CH / 64, (NB * NA) / 64), 256>>>(h, nmask, wb, out);
}